// round 1
// baseline (speedup 1.0000x reference)
#include <cuda_runtime.h>
#include <cstdint>

#define NB       16
#define CIN      256
#define COUT     256
#define HH       32
#define WWID     32
#define HWSZ     1024
#define KWSTRIDE 2304   // CIN * 9 (o-stride in weight)
#define PT       128    // positions per block tile
#define OT       64     // output channels per block tile
#define NTHREADS 256

// packed fp32x2 FMA (SASS FFMA2) — 2x fp32 throughput on sm_103a
__device__ __forceinline__ void ffma2(float2& d, float2 a, float2 b) {
    unsigned long long du = *reinterpret_cast<unsigned long long*>(&d);
    unsigned long long au = *reinterpret_cast<unsigned long long*>(&a);
    unsigned long long bu = *reinterpret_cast<unsigned long long*>(&b);
    asm("fma.rn.f32x2 %0, %1, %2, %0;" : "+l"(du) : "l"(au), "l"(bu));
    d = *reinterpret_cast<float2*>(&du);
}

__global__ __launch_bounds__(NTHREADS)
void deform_conv_kernel(const float* __restrict__ x,
                        const float* __restrict__ offset,
                        const float* __restrict__ weight,
                        float* __restrict__ out)
{
    // smem: 9216 + 18432 + 4096 + 9216 + 4608 = 45568 B (< 48KB static limit)
    __shared__ __align__(16) short4 s_idx[9][PT];     // 4 clipped corner indices
    __shared__ __align__(16) float4 s_w[9][PT];       // 4 corner weights (validity pre-folded)
    __shared__ __align__(16) float  s_x[HWSZ];        // current input channel
    __shared__ __align__(16) float2 s_wt[2][9][OT];   // W duplicated into pairs, double buffered
    __shared__ __align__(16) float  s_v[9][PT];       // deformed im2col slice for current c

    const int tid = threadIdx.x;
    const int n   = blockIdx.z;
    const int oc0 = blockIdx.y * OT;
    const int p0  = blockIdx.x * PT;

    // ---- build sampling tables (once per block) ----
    for (int j = tid; j < 9 * PT; j += NTHREADS) {
        const int k  = j >> 7;
        const int p  = j & (PT - 1);
        const int gp = p0 + p;
        const int yi = gp >> 5;
        const int xi = gp & 31;
        const float2 d2 = *reinterpret_cast<const float2*>(
            offset + ((size_t)n * HWSZ + gp) * 18 + 2 * k);
        const float py = (float)yi + (float)(k / 3 - 1) + d2.x;  // dy first
        const float px = (float)xi + (float)(k % 3 - 1) + d2.y;  // dx second
        const float y0 = floorf(py), x0 = floorf(px);
        const float ly = py - y0, lx = px - x0;
        const float hy = 1.f - ly, hx = 1.f - lx;
        const float vy0 = (y0 >= 0.f  && y0 <= 31.f) ? 1.f : 0.f;
        const float vy1 = (y0 >= -1.f && y0 <= 30.f) ? 1.f : 0.f;
        const float vx0 = (x0 >= 0.f  && x0 <= 31.f) ? 1.f : 0.f;
        const float vx1 = (x0 >= -1.f && x0 <= 30.f) ? 1.f : 0.f;
        const int iy0 = (int)fminf(fmaxf(y0,       0.f), 31.f);
        const int iy1 = (int)fminf(fmaxf(y0 + 1.f, 0.f), 31.f);
        const int ix0 = (int)fminf(fmaxf(x0,       0.f), 31.f);
        const int ix1 = (int)fminf(fmaxf(x0 + 1.f, 0.f), 31.f);
        s_idx[k][p] = make_short4((short)(iy0 * 32 + ix0), (short)(iy0 * 32 + ix1),
                                  (short)(iy1 * 32 + ix0), (short)(iy1 * 32 + ix1));
        s_w[k][p] = make_float4(hy * hx * vy0 * vx0, hy * lx * vy0 * vx1,
                                ly * hx * vy1 * vx0, ly * lx * vy1 * vx1);
    }

    // ---- per-thread W-prefetch metadata (fixed across c) ----
    const float* xbase = x + (size_t)n * CIN * HWSZ;
    int wkk[3], wol[3];
    bool wvalid[3];
    const float* wptr[3];
    #pragma unroll
    for (int r = 0; r < 3; ++r) {
        const int j = tid + r * NTHREADS;
        wvalid[r] = (j < 9 * OT);
        const int ol = wvalid[r] ? (j / 9) : 0;
        const int kk = wvalid[r] ? (j - ol * 9) : 0;
        wol[r] = ol; wkk[r] = kk;
        wptr[r] = weight + (size_t)(oc0 + ol) * KWSTRIDE + kk;
    }

    // ---- preload c = 0 ----
    {
        float4 xr = reinterpret_cast<const float4*>(xbase)[tid];
        reinterpret_cast<float4*>(s_x)[tid] = xr;
        #pragma unroll
        for (int r = 0; r < 3; ++r) {
            if (wvalid[r]) {
                const float wv = *wptr[r];
                s_wt[0][wkk[r]][wol[r]] = make_float2(wv, wv);
                wptr[r] += 9;
            }
        }
    }
    __syncthreads();

    const int to = tid >> 5;   // warp id -> o-subgroup (uniform within warp => broadcast LDS)
    const int tp = tid & 31;   // lane -> position group

    float2 acc[8][2];
    #pragma unroll
    for (int i = 0; i < 8; ++i) {
        acc[i][0] = make_float2(0.f, 0.f);
        acc[i][1] = make_float2(0.f, 0.f);
    }

    int buf = 0;
    for (int c = 0; c < CIN; ++c) {
        // prefetch c+1 into registers (hidden under V-build)
        float4 xr;
        float wr[3];
        const bool has = (c + 1 < CIN);
        if (has) {
            xr = reinterpret_cast<const float4*>(xbase + (size_t)(c + 1) * HWSZ)[tid];
            #pragma unroll
            for (int r = 0; r < 3; ++r)
                if (wvalid[r]) { wr[r] = *wptr[r]; wptr[r] += 9; }
        }

        // build deformed im2col slice V[k][p] for channel c
        for (int j = tid; j < 9 * PT; j += NTHREADS) {
            const int k = j >> 7;
            const int p = j & (PT - 1);
            const short4 id = s_idx[k][p];
            const float4 w  = s_w[k][p];
            s_v[k][p] = w.x * s_x[id.x] + w.y * s_x[id.y]
                      + w.z * s_x[id.z] + w.w * s_x[id.w];
        }
        __syncthreads();   // V ready; all reads of s_x done

        // stash prefetched data (s_x safe to overwrite now; W into other buffer)
        if (has) {
            reinterpret_cast<float4*>(s_x)[tid] = xr;
            #pragma unroll
            for (int r = 0; r < 3; ++r)
                if (wvalid[r])
                    s_wt[buf ^ 1][wkk[r]][wol[r]] = make_float2(wr[r], wr[r]);
        }

        // outer-product GEMM: acc[8 o][4 p] += W[o,c,k] * V[k,p]  (fp32x2)
        #pragma unroll
        for (int k = 0; k < 9; ++k) {
            const float4* wp =
                reinterpret_cast<const float4*>(&s_wt[buf][k][to * 8]);
            const float4 wA = wp[0], wB = wp[1], wC = wp[2], wD = wp[3];
            const float4 vv = *reinterpret_cast<const float4*>(&s_v[k][tp * 4]);
            const float2 v01 = make_float2(vv.x, vv.y);
            const float2 v23 = make_float2(vv.z, vv.w);
            const float2 w0 = make_float2(wA.x, wA.y), w1 = make_float2(wA.z, wA.w);
            const float2 w2 = make_float2(wB.x, wB.y), w3 = make_float2(wB.z, wB.w);
            const float2 w4 = make_float2(wC.x, wC.y), w5 = make_float2(wC.z, wC.w);
            const float2 w6 = make_float2(wD.x, wD.y), w7 = make_float2(wD.z, wD.w);
            ffma2(acc[0][0], w0, v01); ffma2(acc[0][1], w0, v23);
            ffma2(acc[1][0], w1, v01); ffma2(acc[1][1], w1, v23);
            ffma2(acc[2][0], w2, v01); ffma2(acc[2][1], w2, v23);
            ffma2(acc[3][0], w3, v01); ffma2(acc[3][1], w3, v23);
            ffma2(acc[4][0], w4, v01); ffma2(acc[4][1], w4, v23);
            ffma2(acc[5][0], w5, v01); ffma2(acc[5][1], w5, v23);
            ffma2(acc[6][0], w6, v01); ffma2(acc[6][1], w6, v23);
            ffma2(acc[7][0], w7, v01); ffma2(acc[7][1], w7, v23);
        }
        __syncthreads();   // protects s_v / s_x / s_wt for next iteration
        buf ^= 1;
    }

    // ---- epilogue: each thread owns 8 o-rows x 4 contiguous positions ----
    float* obase = out + ((size_t)n * COUT + oc0 + to * 8) * HWSZ + p0 + tp * 4;
    #pragma unroll
    for (int i = 0; i < 8; ++i) {
        const float4 r = make_float4(acc[i][0].x, acc[i][0].y,
                                     acc[i][1].x, acc[i][1].y);
        *reinterpret_cast<float4*>(obase + (size_t)i * HWSZ) = r;
    }
}

extern "C" void kernel_launch(void* const* d_in, const int* in_sizes, int n_in,
                              void* d_out, int out_size)
{
    const float* x      = (const float*)d_in[0];
    const float* offset = (const float*)d_in[1];
    const float* weight = (const float*)d_in[2];
    float* out          = (float*)d_out;

    dim3 grid(HWSZ / PT, COUT / OT, NB);   // 8 x 4 x 16 = 512 blocks
    deform_conv_kernel<<<grid, NTHREADS>>>(x, offset, weight, out);
}